// round 5
// baseline (speedup 1.0000x reference)
#include <cuda_runtime.h>
#include <cuda_bf16.h>

// CTC forward for two tasks (PyTorch semantics: blank=0, mean of loss/target_len,
// zero_infinity). One block per (task, batch) element = 64 blocks, 128 threads.
//
// Register-blocked wavefront: each thread owns R=4 consecutive extended-target
// positions l = 4*tid .. 4*tid+3 as (mantissa in [1,2), int32 exponent) pairs.
// Because 'skip' transitions only exist at odd l, the only cross-thread operand
// per step is the left neighbor's slot 3 -> one (m,e) via 2 warp shuffles;
// warp boundaries use an 8-byte double-buffered smem slot. No MUFU on the
// critical path: per-symbol probs p=ex2(lp) are prefetched one step ahead.

#define LOG2E 1.4426950408889634f
#define LN2   0.6931471805599453f
#define BATCH 32
#define TMAX  2000
#define NT    128
#define EDEAD (-(1 << 28))

static __device__ float        g_partial[64];
static __device__ unsigned int g_count = 0;

__device__ __forceinline__ float ex2(float x) {
    float y; asm("ex2.approx.f32 %0, %1;" : "=f"(y) : "f"(x)); return y;
}
__device__ __forceinline__ float lg2(float x) {
    float y; asm("lg2.approx.f32 %0, %1;" : "=f"(y) : "f"(x)); return y;
}

// 3-term: alpha' = p * (ma*2^ea + mb*2^eb + mc*2^ec), result renormalized.
__device__ __forceinline__ void upd3(float ma, int ea, float mb, int eb,
                                     float mc, int ec, float p,
                                     float& mo, int& eo) {
    int em = max(ea, max(eb, ec));
    float sa = __int_as_float(max(ea - em + 127, 0) << 23);
    float sb = __int_as_float(max(eb - em + 127, 0) << 23);
    float sc = __int_as_float(max(ec - em + 127, 0) << 23);
    float s  = fmaf(mc, sc, fmaf(mb, sb, ma * sa));   // in [1, 6)
    float mp = p * s;                                  // normal float > 0
    int bb = __float_as_int(mp);
    eo = em + ((bb >> 23) - 127);
    mo = __int_as_float((bb & 0x007FFFFF) | 0x3F800000);
}
__device__ __forceinline__ void upd2(float ma, int ea, float mb, int eb,
                                     float p, float& mo, int& eo) {
    int em = max(ea, eb);
    float sa = __int_as_float(max(ea - em + 127, 0) << 23);
    float sb = __int_as_float(max(eb - em + 127, 0) << 23);
    float s  = fmaf(mb, sb, ma * sa);
    float mp = p * s;
    int bb = __float_as_int(mp);
    eo = em + ((bb >> 23) - 127);
    mo = __int_as_float((bb & 0x007FFFFF) | 0x3F800000);
}
__device__ __forceinline__ float pow2c(int dp127) {   // 2^d, d<=0, clamped
    return __int_as_float(max(dp127, 0) << 23);
}

__global__ void __launch_bounds__(NT, 1)
ctc_forward_kernel(const float* __restrict__ elog, const float* __restrict__ plog,
                   const int* __restrict__ etgt, const int* __restrict__ ptgt,
                   const int* __restrict__ eil,  const int* __restrict__ pil,
                   const int* __restrict__ etl,  const int* __restrict__ ptl,
                   float* __restrict__ out)
{
    __shared__ float sD[TMAX];        // log2 softmax denominator per timestep
    __shared__ float sStage[2][64];   // staged log2-prob row: x*log2e - D[t]
    __shared__ uint2 sBnd[2][4];      // warp-boundary slot3 (m,e), double-buffered
    __shared__ float sFm[NT * 4];     // final mantissas
    __shared__ int   sFe[NT * 4];     // final exponents
    __shared__ int   sLast;

    const int task = blockIdx.x >> 5;   // 0 = error (C=4), 1 = phoneme (C=64)
    const int b    = blockIdx.x & 31;
    const int tid  = threadIdx.x;
    const int lane = tid & 31;
    const int wid  = tid >> 5;

    const float* logits;
    const int*   targets;
    int C, S, ilen, tlen;
    if (task == 0) {
        C = 4;  S = 50;
        logits  = elog + (size_t)b * TMAX * 4;
        targets = etgt + b * 50;
        ilen = eil[b]; tlen = etl[b];
    } else {
        C = 64; S = 200;
        logits  = plog + (size_t)b * TMAX * 64;
        targets = ptgt + b * 200;
        ilen = pil[b]; tlen = ptl[b];
    }
    const int L    = 2 * S + 1;
    const int Teff = min(TMAX, max(ilen, 1));

    // ---------- Phase 1: log2-sum-exp denominators ----------
    for (int t = tid; t < Teff; t += NT) {
        const float* row = logits + (size_t)t * C;
        float s = 0.f;
        for (int k = 0; k < C; k += 4) {
            float4 v = *reinterpret_cast<const float4*>(row + k);
            s += ex2(v.x * LOG2E) + ex2(v.y * LOG2E)
               + ex2(v.z * LOG2E) + ex2(v.w * LOG2E);
        }
        sD[t] = lg2(s);
    }
    __syncthreads();

    // ---------- Per-thread slot setup: l = 4*tid + {0,1,2,3} ----------
    const int  l0 = 4 * tid;
    const bool v0 = (l0     < L), v1 = (l0 + 1 < L),
               v2 = (l0 + 2 < L), v3 = (l0 + 3 < L);
    const int  j1  = min(2 * tid,     S - 1);
    const int  j1m = max(2 * tid - 1, 0);
    const int  j3  = min(2 * tid + 1, S - 1);
    const int  ext1 = targets[j1];
    const int  ext3 = targets[j3];
    const bool skip1 = (tid >= 1) && (ext1 != targets[j1m]);
    const bool skip3 = (ext3 != ext1);

    // ---------- alpha init (t = 0) ----------
    float m0 = 1.f, m1 = 1.f, m2 = 1.f, m3 = 1.f;
    int   e0 = EDEAD, e1 = EDEAD, e2 = EDEAD, e3 = EDEAD;
    if (tid == 0) {
        float a = ex2(fmaxf(fmaf(logits[0],    LOG2E, -sD[0]), -120.f));
        int bb = __float_as_int(a);
        e0 = (bb >> 23) - 127; m0 = __int_as_float((bb & 0x007FFFFF) | 0x3F800000);
        a = ex2(fmaxf(fmaf(logits[ext1], LOG2E, -sD[0]), -120.f));
        bb = __float_as_int(a);
        e1 = (bb >> 23) - 127; m1 = __int_as_float((bb & 0x007FFFFF) | 0x3F800000);
    }
    if (lane == 31) sBnd[0][wid] = make_uint2(__float_as_uint(m3), (unsigned)e3);

    if (tid < C && 1 < Teff) sStage[1][tid] = fmaf(logits[C + tid], LOG2E, -sD[1]);
    float gpre = 0.f;
    if (tid < C && 2 < Teff) gpre = logits[(size_t)2 * C + tid];
    __syncthreads();

    // Prefetch symbol probs for step t=1 (linear domain, normal floats).
    float pb = ex2(fmaxf(sStage[1][0],    -120.f));
    float p1 = ex2(fmaxf(sStage[1][ext1], -120.f));
    float p3 = ex2(fmaxf(sStage[1][ext3], -120.f));

    // ---------- Phase 2: forward scan ----------
    for (int t = 1; t < Teff; ++t) {
        const int pp = t & 1, q = pp ^ 1;

        // Stage row t+1 (prefetched last iteration); prefetch row t+2.
        if (tid < C) {
            if (t + 1 < Teff) sStage[q][tid] = fmaf(gpre, LOG2E, -sD[t + 1]);
            if (t + 2 < Teff) gpre = logits[(size_t)(t + 2) * C + tid];
        }

        // Left neighbor's OLD slot 3 (only cross-thread operand).
        float nm3 = __shfl_up_sync(0xffffffffu, m3, 1);
        int   ne3 = __shfl_up_sync(0xffffffffu, e3, 1);
        if (lane == 0) {
            if (wid > 0) {
                uint2 v = sBnd[q][wid - 1];
                nm3 = __uint_as_float(v.x); ne3 = (int)v.y;
            } else { nm3 = 1.f; ne3 = EDEAD; }
        }

        float o0m, o1m, o2m, o3m; int o0e, o1e, o2e, o3e;
        upd2(m0, e0, nm3, ne3, pb, o0m, o0e);                           // blank
        upd3(m1, e1, m0, e0, nm3, skip1 ? ne3 : EDEAD, p1, o1m, o1e);   // sym1
        upd2(m2, e2, m1, e1, pb, o2m, o2e);                             // blank
        upd3(m3, e3, m2, e2, m1, skip3 ? e1 : EDEAD, p3, o3m, o3e);     // sym3

        m0 = o0m; e0 = v0 ? o0e : EDEAD;
        m1 = o1m; e1 = v1 ? o1e : EDEAD;
        m2 = o2m; e2 = v2 ? o2e : EDEAD;
        m3 = o3m; e3 = v3 ? o3e : EDEAD;

        if (lane == 31) sBnd[pp][wid] = make_uint2(__float_as_uint(m3), (unsigned)e3);

        __syncthreads();

        // Prefetch symbol probs for step t+1 (off the critical path).
        pb = ex2(fmaxf(sStage[q][0],    -120.f));
        p1 = ex2(fmaxf(sStage[q][ext1], -120.f));
        p3 = ex2(fmaxf(sStage[q][ext3], -120.f));
    }

    // ---------- Publish final alphas ----------
    sFm[l0] = m0; sFe[l0] = e0;
    sFm[l0 + 1] = m1; sFe[l0 + 1] = e1;
    sFm[l0 + 2] = m2; sFe[l0 + 2] = e2;
    sFm[l0 + 3] = m3; sFe[l0 + 3] = e3;
    __syncthreads();

    // ---------- Final loss + fused deterministic reduction ----------
    if (tid == 0) {
        const int iL = 2 * tlen - 1, iB = 2 * tlen;
        int   eL = sFe[iL], eB = sFe[iB];
        float mL = sFm[iL], mB = sFm[iB];
        int   em = max(eL, eB);
        float ss = mL * pow2c(eL + 127 - em) + mB * pow2c(eB + 127 - em);
        float loss = -((float)em + lg2(ss)) * LN2;     // nats
        if (em < -(1 << 27)) loss = 0.f;               // no feasible path => inf
        if (!(loss <= 1e29f)) loss = 0.f;              // zero_infinity / NaN
        g_partial[blockIdx.x] = loss / (float)tlen * (1.0f / BATCH);
        __threadfence();
        unsigned tk = atomicAdd(&g_count, 1u);
        sLast = (tk == 63u);
    }
    __syncthreads();
    if (sLast && tid == 0) {
        __threadfence();
        float s = 0.f;
        #pragma unroll
        for (int i = 0; i < 64; ++i) {
            float v;
            asm volatile("ld.global.cg.f32 %0, [%1];" : "=f"(v) : "l"(g_partial + i));
            s += v;
        }
        out[0] = s;
        g_count = 0;   // reset for graph replay
    }
}

extern "C" void kernel_launch(void* const* d_in, const int* in_sizes, int n_in,
                              void* d_out, int out_size)
{
    const float* elog = (const float*)d_in[0];
    const float* plog = (const float*)d_in[1];
    const int*   etgt = (const int*)d_in[2];
    const int*   ptgt = (const int*)d_in[3];
    const int*   eil  = (const int*)d_in[4];
    const int*   pil  = (const int*)d_in[5];
    const int*   etl  = (const int*)d_in[6];
    const int*   ptl  = (const int*)d_in[7];
    float* out = (float*)d_out;

    ctc_forward_kernel<<<64, NT>>>(elog, plog, etgt, ptgt,
                                   eil, pil, etl, ptl, out);
}

// round 6
// speedup vs baseline: 1.0046x; 1.0046x over previous
#include <cuda_runtime.h>
#include <cuda_bf16.h>

// CTC forward for two tasks (PyTorch semantics: blank=0, mean of loss/target_len,
// zero_infinity). One block per (task, batch) element = 64 blocks, 128 threads.
//
// Register-blocked wavefront: each thread owns R=4 consecutive extended-target
// positions l = 4*tid .. 4*tid+3 as (mantissa in [1,2), int32 exponent) pairs.
// Because 'skip' transitions only exist at odd l, the only cross-thread operand
// per step is the left neighbor's slot 3 -> one (m,e) via 2 warp shuffles;
// warp boundaries use an 8-byte double-buffered smem slot. No MUFU on the
// critical path: per-symbol probs p=ex2(lp) are prefetched one step ahead.

#define LOG2E 1.4426950408889634f
#define LN2   0.6931471805599453f
#define BATCH 32
#define TMAX  2000
#define NT    128
#define EDEAD (-(1 << 28))

static __device__ float        g_partial[64];
static __device__ unsigned int g_count = 0;

__device__ __forceinline__ float ex2(float x) {
    float y; asm("ex2.approx.f32 %0, %1;" : "=f"(y) : "f"(x)); return y;
}
__device__ __forceinline__ float lg2(float x) {
    float y; asm("lg2.approx.f32 %0, %1;" : "=f"(y) : "f"(x)); return y;
}

// 3-term: alpha' = p * (ma*2^ea + mb*2^eb + mc*2^ec), result renormalized.
__device__ __forceinline__ void upd3(float ma, int ea, float mb, int eb,
                                     float mc, int ec, float p,
                                     float& mo, int& eo) {
    int em = max(ea, max(eb, ec));
    float sa = __int_as_float(max(ea - em + 127, 0) << 23);
    float sb = __int_as_float(max(eb - em + 127, 0) << 23);
    float sc = __int_as_float(max(ec - em + 127, 0) << 23);
    float s  = fmaf(mc, sc, fmaf(mb, sb, ma * sa));   // in [1, 6)
    float mp = p * s;                                  // normal float > 0
    int bb = __float_as_int(mp);
    eo = em + ((bb >> 23) - 127);
    mo = __int_as_float((bb & 0x007FFFFF) | 0x3F800000);
}
__device__ __forceinline__ void upd2(float ma, int ea, float mb, int eb,
                                     float p, float& mo, int& eo) {
    int em = max(ea, eb);
    float sa = __int_as_float(max(ea - em + 127, 0) << 23);
    float sb = __int_as_float(max(eb - em + 127, 0) << 23);
    float s  = fmaf(mb, sb, ma * sa);
    float mp = p * s;
    int bb = __float_as_int(mp);
    eo = em + ((bb >> 23) - 127);
    mo = __int_as_float((bb & 0x007FFFFF) | 0x3F800000);
}
__device__ __forceinline__ float pow2c(int dp127) {   // 2^d, d<=0, clamped
    return __int_as_float(max(dp127, 0) << 23);
}

__global__ void __launch_bounds__(NT, 1)
ctc_forward_kernel(const float* __restrict__ elog, const float* __restrict__ plog,
                   const int* __restrict__ etgt, const int* __restrict__ ptgt,
                   const int* __restrict__ eil,  const int* __restrict__ pil,
                   const int* __restrict__ etl,  const int* __restrict__ ptl,
                   float* __restrict__ out)
{
    __shared__ float sD[TMAX];        // log2 softmax denominator per timestep
    __shared__ float sStage[2][64];   // staged log2-prob row: x*log2e - D[t]
    __shared__ uint2 sBnd[2][4];      // warp-boundary slot3 (m,e), double-buffered
    __shared__ float sFm[NT * 4];     // final mantissas
    __shared__ int   sFe[NT * 4];     // final exponents
    __shared__ int   sLast;

    const int task = blockIdx.x >> 5;   // 0 = error (C=4), 1 = phoneme (C=64)
    const int b    = blockIdx.x & 31;
    const int tid  = threadIdx.x;
    const int lane = tid & 31;
    const int wid  = tid >> 5;

    const float* logits;
    const int*   targets;
    int C, S, ilen, tlen;
    if (task == 0) {
        C = 4;  S = 50;
        logits  = elog + (size_t)b * TMAX * 4;
        targets = etgt + b * 50;
        ilen = eil[b]; tlen = etl[b];
    } else {
        C = 64; S = 200;
        logits  = plog + (size_t)b * TMAX * 64;
        targets = ptgt + b * 200;
        ilen = pil[b]; tlen = ptl[b];
    }
    const int L    = 2 * S + 1;
    const int Teff = min(TMAX, max(ilen, 1));

    // ---------- Phase 1: log2-sum-exp denominators ----------
    for (int t = tid; t < Teff; t += NT) {
        const float* row = logits + (size_t)t * C;
        float s = 0.f;
        for (int k = 0; k < C; k += 4) {
            float4 v = *reinterpret_cast<const float4*>(row + k);
            s += ex2(v.x * LOG2E) + ex2(v.y * LOG2E)
               + ex2(v.z * LOG2E) + ex2(v.w * LOG2E);
        }
        sD[t] = lg2(s);
    }
    __syncthreads();

    // ---------- Per-thread slot setup: l = 4*tid + {0,1,2,3} ----------
    const int  l0 = 4 * tid;
    const bool v0 = (l0     < L), v1 = (l0 + 1 < L),
               v2 = (l0 + 2 < L), v3 = (l0 + 3 < L);
    const int  j1  = min(2 * tid,     S - 1);
    const int  j1m = max(2 * tid - 1, 0);
    const int  j3  = min(2 * tid + 1, S - 1);
    const int  ext1 = targets[j1];
    const int  ext3 = targets[j3];
    const bool skip1 = (tid >= 1) && (ext1 != targets[j1m]);
    const bool skip3 = (ext3 != ext1);

    // ---------- alpha init (t = 0) ----------
    float m0 = 1.f, m1 = 1.f, m2 = 1.f, m3 = 1.f;
    int   e0 = EDEAD, e1 = EDEAD, e2 = EDEAD, e3 = EDEAD;
    if (tid == 0) {
        float a = ex2(fmaxf(fmaf(logits[0],    LOG2E, -sD[0]), -120.f));
        int bb = __float_as_int(a);
        e0 = (bb >> 23) - 127; m0 = __int_as_float((bb & 0x007FFFFF) | 0x3F800000);
        a = ex2(fmaxf(fmaf(logits[ext1], LOG2E, -sD[0]), -120.f));
        bb = __float_as_int(a);
        e1 = (bb >> 23) - 127; m1 = __int_as_float((bb & 0x007FFFFF) | 0x3F800000);
    }
    if (lane == 31) sBnd[0][wid] = make_uint2(__float_as_uint(m3), (unsigned)e3);

    if (tid < C && 1 < Teff) sStage[1][tid] = fmaf(logits[C + tid], LOG2E, -sD[1]);
    float gpre = 0.f;
    if (tid < C && 2 < Teff) gpre = logits[(size_t)2 * C + tid];
    __syncthreads();

    // Prefetch symbol probs for step t=1 (linear domain, normal floats).
    float pb = ex2(fmaxf(sStage[1][0],    -120.f));
    float p1 = ex2(fmaxf(sStage[1][ext1], -120.f));
    float p3 = ex2(fmaxf(sStage[1][ext3], -120.f));

    // ---------- Phase 2: forward scan ----------
    for (int t = 1; t < Teff; ++t) {
        const int pp = t & 1, q = pp ^ 1;

        // Stage row t+1 (prefetched last iteration); prefetch row t+2.
        if (tid < C) {
            if (t + 1 < Teff) sStage[q][tid] = fmaf(gpre, LOG2E, -sD[t + 1]);
            if (t + 2 < Teff) gpre = logits[(size_t)(t + 2) * C + tid];
        }

        // Left neighbor's OLD slot 3 (only cross-thread operand).
        float nm3 = __shfl_up_sync(0xffffffffu, m3, 1);
        int   ne3 = __shfl_up_sync(0xffffffffu, e3, 1);
        if (lane == 0) {
            if (wid > 0) {
                uint2 v = sBnd[q][wid - 1];
                nm3 = __uint_as_float(v.x); ne3 = (int)v.y;
            } else { nm3 = 1.f; ne3 = EDEAD; }
        }

        float o0m, o1m, o2m, o3m; int o0e, o1e, o2e, o3e;
        upd2(m0, e0, nm3, ne3, pb, o0m, o0e);                           // blank
        upd3(m1, e1, m0, e0, nm3, skip1 ? ne3 : EDEAD, p1, o1m, o1e);   // sym1
        upd2(m2, e2, m1, e1, pb, o2m, o2e);                             // blank
        upd3(m3, e3, m2, e2, m1, skip3 ? e1 : EDEAD, p3, o3m, o3e);     // sym3

        m0 = o0m; e0 = v0 ? o0e : EDEAD;
        m1 = o1m; e1 = v1 ? o1e : EDEAD;
        m2 = o2m; e2 = v2 ? o2e : EDEAD;
        m3 = o3m; e3 = v3 ? o3e : EDEAD;

        if (lane == 31) sBnd[pp][wid] = make_uint2(__float_as_uint(m3), (unsigned)e3);

        __syncthreads();

        // Prefetch symbol probs for step t+1 (off the critical path).
        pb = ex2(fmaxf(sStage[q][0],    -120.f));
        p1 = ex2(fmaxf(sStage[q][ext1], -120.f));
        p3 = ex2(fmaxf(sStage[q][ext3], -120.f));
    }

    // ---------- Publish final alphas ----------
    sFm[l0] = m0; sFe[l0] = e0;
    sFm[l0 + 1] = m1; sFe[l0 + 1] = e1;
    sFm[l0 + 2] = m2; sFe[l0 + 2] = e2;
    sFm[l0 + 3] = m3; sFe[l0 + 3] = e3;
    __syncthreads();

    // ---------- Final loss + fused deterministic reduction ----------
    if (tid == 0) {
        const int iL = 2 * tlen - 1, iB = 2 * tlen;
        int   eL = sFe[iL], eB = sFe[iB];
        float mL = sFm[iL], mB = sFm[iB];
        int   em = max(eL, eB);
        float ss = mL * pow2c(eL + 127 - em) + mB * pow2c(eB + 127 - em);
        float loss = -((float)em + lg2(ss)) * LN2;     // nats
        if (em < -(1 << 27)) loss = 0.f;               // no feasible path => inf
        if (!(loss <= 1e29f)) loss = 0.f;              // zero_infinity / NaN
        g_partial[blockIdx.x] = loss / (float)tlen * (1.0f / BATCH);
        __threadfence();
        unsigned tk = atomicAdd(&g_count, 1u);
        sLast = (tk == 63u);
    }
    __syncthreads();
    if (sLast && tid == 0) {
        __threadfence();
        float s = 0.f;
        #pragma unroll
        for (int i = 0; i < 64; ++i) {
            float v;
            asm volatile("ld.global.cg.f32 %0, [%1];" : "=f"(v) : "l"(g_partial + i));
            s += v;
        }
        out[0] = s;
        g_count = 0;   // reset for graph replay
    }
}

extern "C" void kernel_launch(void* const* d_in, const int* in_sizes, int n_in,
                              void* d_out, int out_size)
{
    const float* elog = (const float*)d_in[0];
    const float* plog = (const float*)d_in[1];
    const int*   etgt = (const int*)d_in[2];
    const int*   ptgt = (const int*)d_in[3];
    const int*   eil  = (const int*)d_in[4];
    const int*   pil  = (const int*)d_in[5];
    const int*   etl  = (const int*)d_in[6];
    const int*   ptl  = (const int*)d_in[7];
    float* out = (float*)d_out;

    ctc_forward_kernel<<<64, NT>>>(elog, plog, etgt, ptgt,
                                   eil, pil, etl, ptl, out);
}

// round 7
// speedup vs baseline: 1.0050x; 1.0004x over previous
#include <cuda_runtime.h>
#include <cuda_bf16.h>

// CTC forward for two tasks (PyTorch semantics: blank=0, mean of loss/target_len,
// zero_infinity). One block per (task, batch) element = 64 blocks, 128 threads.
//
// Register-blocked wavefront: each thread owns R=4 consecutive extended-target
// positions l = 4*tid .. 4*tid+3 as (mantissa in [1,2), int32 exponent) pairs.
// Because 'skip' transitions only exist at odd l, the only cross-thread operand
// per step is the left neighbor's slot 3 -> one (m,e) via 2 warp shuffles;
// warp boundaries use an 8-byte double-buffered smem slot. No MUFU on the
// critical path: per-symbol probs p=ex2(lp) are prefetched one step ahead.

#define LOG2E 1.4426950408889634f
#define LN2   0.6931471805599453f
#define BATCH 32
#define TMAX  2000
#define NT    128
#define EDEAD (-(1 << 28))

static __device__ float        g_partial[64];
static __device__ unsigned int g_count = 0;

__device__ __forceinline__ float ex2(float x) {
    float y; asm("ex2.approx.f32 %0, %1;" : "=f"(y) : "f"(x)); return y;
}
__device__ __forceinline__ float lg2(float x) {
    float y; asm("lg2.approx.f32 %0, %1;" : "=f"(y) : "f"(x)); return y;
}

// 3-term: alpha' = p * (ma*2^ea + mb*2^eb + mc*2^ec), result renormalized.
__device__ __forceinline__ void upd3(float ma, int ea, float mb, int eb,
                                     float mc, int ec, float p,
                                     float& mo, int& eo) {
    int em = max(ea, max(eb, ec));
    float sa = __int_as_float(max(ea - em + 127, 0) << 23);
    float sb = __int_as_float(max(eb - em + 127, 0) << 23);
    float sc = __int_as_float(max(ec - em + 127, 0) << 23);
    float s  = fmaf(mc, sc, fmaf(mb, sb, ma * sa));   // in [1, 6)
    float mp = p * s;                                  // normal float > 0
    int bb = __float_as_int(mp);
    eo = em + ((bb >> 23) - 127);
    mo = __int_as_float((bb & 0x007FFFFF) | 0x3F800000);
}
__device__ __forceinline__ void upd2(float ma, int ea, float mb, int eb,
                                     float p, float& mo, int& eo) {
    int em = max(ea, eb);
    float sa = __int_as_float(max(ea - em + 127, 0) << 23);
    float sb = __int_as_float(max(eb - em + 127, 0) << 23);
    float s  = fmaf(mb, sb, ma * sa);
    float mp = p * s;
    int bb = __float_as_int(mp);
    eo = em + ((bb >> 23) - 127);
    mo = __int_as_float((bb & 0x007FFFFF) | 0x3F800000);
}
__device__ __forceinline__ float pow2c(int dp127) {   // 2^d, d<=0, clamped
    return __int_as_float(max(dp127, 0) << 23);
}

__global__ void __launch_bounds__(NT, 1)
ctc_forward_kernel(const float* __restrict__ elog, const float* __restrict__ plog,
                   const int* __restrict__ etgt, const int* __restrict__ ptgt,
                   const int* __restrict__ eil,  const int* __restrict__ pil,
                   const int* __restrict__ etl,  const int* __restrict__ ptl,
                   float* __restrict__ out)
{
    __shared__ float sD[TMAX];        // log2 softmax denominator per timestep
    __shared__ float sStage[2][64];   // staged log2-prob row: x*log2e - D[t]
    __shared__ uint2 sBnd[2][4];      // warp-boundary slot3 (m,e), double-buffered
    __shared__ float sFm[NT * 4];     // final mantissas
    __shared__ int   sFe[NT * 4];     // final exponents
    __shared__ int   sLast;

    const int task = blockIdx.x >> 5;   // 0 = error (C=4), 1 = phoneme (C=64)
    const int b    = blockIdx.x & 31;
    const int tid  = threadIdx.x;
    const int lane = tid & 31;
    const int wid  = tid >> 5;

    const float* logits;
    const int*   targets;
    int C, S, ilen, tlen;
    if (task == 0) {
        C = 4;  S = 50;
        logits  = elog + (size_t)b * TMAX * 4;
        targets = etgt + b * 50;
        ilen = eil[b]; tlen = etl[b];
    } else {
        C = 64; S = 200;
        logits  = plog + (size_t)b * TMAX * 64;
        targets = ptgt + b * 200;
        ilen = pil[b]; tlen = ptl[b];
    }
    const int L    = 2 * S + 1;
    const int Teff = min(TMAX, max(ilen, 1));

    // ---------- Phase 1: log2-sum-exp denominators ----------
    for (int t = tid; t < Teff; t += NT) {
        const float* row = logits + (size_t)t * C;
        float s = 0.f;
        for (int k = 0; k < C; k += 4) {
            float4 v = *reinterpret_cast<const float4*>(row + k);
            s += ex2(v.x * LOG2E) + ex2(v.y * LOG2E)
               + ex2(v.z * LOG2E) + ex2(v.w * LOG2E);
        }
        sD[t] = lg2(s);
    }
    __syncthreads();

    // ---------- Per-thread slot setup: l = 4*tid + {0,1,2,3} ----------
    const int  l0 = 4 * tid;
    const bool v0 = (l0     < L), v1 = (l0 + 1 < L),
               v2 = (l0 + 2 < L), v3 = (l0 + 3 < L);
    const int  j1  = min(2 * tid,     S - 1);
    const int  j1m = max(2 * tid - 1, 0);
    const int  j3  = min(2 * tid + 1, S - 1);
    const int  ext1 = targets[j1];
    const int  ext3 = targets[j3];
    const bool skip1 = (tid >= 1) && (ext1 != targets[j1m]);
    const bool skip3 = (ext3 != ext1);

    // ---------- alpha init (t = 0) ----------
    float m0 = 1.f, m1 = 1.f, m2 = 1.f, m3 = 1.f;
    int   e0 = EDEAD, e1 = EDEAD, e2 = EDEAD, e3 = EDEAD;
    if (tid == 0) {
        float a = ex2(fmaxf(fmaf(logits[0],    LOG2E, -sD[0]), -120.f));
        int bb = __float_as_int(a);
        e0 = (bb >> 23) - 127; m0 = __int_as_float((bb & 0x007FFFFF) | 0x3F800000);
        a = ex2(fmaxf(fmaf(logits[ext1], LOG2E, -sD[0]), -120.f));
        bb = __float_as_int(a);
        e1 = (bb >> 23) - 127; m1 = __int_as_float((bb & 0x007FFFFF) | 0x3F800000);
    }
    if (lane == 31) sBnd[0][wid] = make_uint2(__float_as_uint(m3), (unsigned)e3);

    if (tid < C && 1 < Teff) sStage[1][tid] = fmaf(logits[C + tid], LOG2E, -sD[1]);
    float gpre = 0.f;
    if (tid < C && 2 < Teff) gpre = logits[(size_t)2 * C + tid];
    __syncthreads();

    // Prefetch symbol probs for step t=1 (linear domain, normal floats).
    float pb = ex2(fmaxf(sStage[1][0],    -120.f));
    float p1 = ex2(fmaxf(sStage[1][ext1], -120.f));
    float p3 = ex2(fmaxf(sStage[1][ext3], -120.f));

    // ---------- Phase 2: forward scan ----------
    for (int t = 1; t < Teff; ++t) {
        const int pp = t & 1, q = pp ^ 1;

        // Stage row t+1 (prefetched last iteration); prefetch row t+2.
        if (tid < C) {
            if (t + 1 < Teff) sStage[q][tid] = fmaf(gpre, LOG2E, -sD[t + 1]);
            if (t + 2 < Teff) gpre = logits[(size_t)(t + 2) * C + tid];
        }

        // Left neighbor's OLD slot 3 (only cross-thread operand).
        float nm3 = __shfl_up_sync(0xffffffffu, m3, 1);
        int   ne3 = __shfl_up_sync(0xffffffffu, e3, 1);
        if (lane == 0) {
            if (wid > 0) {
                uint2 v = sBnd[q][wid - 1];
                nm3 = __uint_as_float(v.x); ne3 = (int)v.y;
            } else { nm3 = 1.f; ne3 = EDEAD; }
        }

        float o0m, o1m, o2m, o3m; int o0e, o1e, o2e, o3e;
        upd2(m0, e0, nm3, ne3, pb, o0m, o0e);                           // blank
        upd3(m1, e1, m0, e0, nm3, skip1 ? ne3 : EDEAD, p1, o1m, o1e);   // sym1
        upd2(m2, e2, m1, e1, pb, o2m, o2e);                             // blank
        upd3(m3, e3, m2, e2, m1, skip3 ? e1 : EDEAD, p3, o3m, o3e);     // sym3

        m0 = o0m; e0 = v0 ? o0e : EDEAD;
        m1 = o1m; e1 = v1 ? o1e : EDEAD;
        m2 = o2m; e2 = v2 ? o2e : EDEAD;
        m3 = o3m; e3 = v3 ? o3e : EDEAD;

        if (lane == 31) sBnd[pp][wid] = make_uint2(__float_as_uint(m3), (unsigned)e3);

        __syncthreads();

        // Prefetch symbol probs for step t+1 (off the critical path).
        pb = ex2(fmaxf(sStage[q][0],    -120.f));
        p1 = ex2(fmaxf(sStage[q][ext1], -120.f));
        p3 = ex2(fmaxf(sStage[q][ext3], -120.f));
    }

    // ---------- Publish final alphas ----------
    sFm[l0] = m0; sFe[l0] = e0;
    sFm[l0 + 1] = m1; sFe[l0 + 1] = e1;
    sFm[l0 + 2] = m2; sFe[l0 + 2] = e2;
    sFm[l0 + 3] = m3; sFe[l0 + 3] = e3;
    __syncthreads();

    // ---------- Final loss + fused deterministic reduction ----------
    if (tid == 0) {
        const int iL = 2 * tlen - 1, iB = 2 * tlen;
        int   eL = sFe[iL], eB = sFe[iB];
        float mL = sFm[iL], mB = sFm[iB];
        int   em = max(eL, eB);
        float ss = mL * pow2c(eL + 127 - em) + mB * pow2c(eB + 127 - em);
        float loss = -((float)em + lg2(ss)) * LN2;     // nats
        if (em < -(1 << 27)) loss = 0.f;               // no feasible path => inf
        if (!(loss <= 1e29f)) loss = 0.f;              // zero_infinity / NaN
        g_partial[blockIdx.x] = loss / (float)tlen * (1.0f / BATCH);
        __threadfence();
        unsigned tk = atomicAdd(&g_count, 1u);
        sLast = (tk == 63u);
    }
    __syncthreads();
    if (sLast && tid == 0) {
        __threadfence();
        float s = 0.f;
        #pragma unroll
        for (int i = 0; i < 64; ++i) {
            float v;
            asm volatile("ld.global.cg.f32 %0, [%1];" : "=f"(v) : "l"(g_partial + i));
            s += v;
        }
        out[0] = s;
        g_count = 0;   // reset for graph replay
    }
}

extern "C" void kernel_launch(void* const* d_in, const int* in_sizes, int n_in,
                              void* d_out, int out_size)
{
    const float* elog = (const float*)d_in[0];
    const float* plog = (const float*)d_in[1];
    const int*   etgt = (const int*)d_in[2];
    const int*   ptgt = (const int*)d_in[3];
    const int*   eil  = (const int*)d_in[4];
    const int*   pil  = (const int*)d_in[5];
    const int*   etl  = (const int*)d_in[6];
    const int*   ptl  = (const int*)d_in[7];
    float* out = (float*)d_out;

    ctc_forward_kernel<<<64, NT>>>(elog, plog, etgt, ptgt,
                                   eil, pil, etl, ptl, out);
}

// round 8
// speedup vs baseline: 1.0114x; 1.0064x over previous
#include <cuda_runtime.h>
#include <cuda_bf16.h>

// CTC forward for two tasks (PyTorch semantics: blank=0, mean of loss/target_len,
// zero_infinity). One block per (task, batch) element = 64 blocks, 128 threads.
//
// Register-blocked wavefront: each thread owns R=4 consecutive extended-target
// positions l = 4*tid .. 4*tid+3 as (mantissa in [1,2), int32 exponent) pairs.
// Because 'skip' transitions only exist at odd l, the only cross-thread operand
// per step is the left neighbor's slot 3 -> one (m,e) via 2 warp shuffles;
// warp boundaries use an 8-byte double-buffered smem slot. No MUFU on the
// critical path: per-symbol probs p=ex2(lp) are prefetched one step ahead.

#define LOG2E 1.4426950408889634f
#define LN2   0.6931471805599453f
#define BATCH 32
#define TMAX  2000
#define NT    128
#define EDEAD (-(1 << 28))

static __device__ float        g_partial[64];
static __device__ unsigned int g_count = 0;

__device__ __forceinline__ float ex2(float x) {
    float y; asm("ex2.approx.f32 %0, %1;" : "=f"(y) : "f"(x)); return y;
}
__device__ __forceinline__ float lg2(float x) {
    float y; asm("lg2.approx.f32 %0, %1;" : "=f"(y) : "f"(x)); return y;
}

// 3-term: alpha' = p * (ma*2^ea + mb*2^eb + mc*2^ec), result renormalized.
__device__ __forceinline__ void upd3(float ma, int ea, float mb, int eb,
                                     float mc, int ec, float p,
                                     float& mo, int& eo) {
    int em = max(ea, max(eb, ec));
    float sa = __int_as_float(max(ea - em + 127, 0) << 23);
    float sb = __int_as_float(max(eb - em + 127, 0) << 23);
    float sc = __int_as_float(max(ec - em + 127, 0) << 23);
    float s  = fmaf(mc, sc, fmaf(mb, sb, ma * sa));   // in [1, 6)
    float mp = p * s;                                  // normal float > 0
    int bb = __float_as_int(mp);
    eo = em + ((bb >> 23) - 127);
    mo = __int_as_float((bb & 0x007FFFFF) | 0x3F800000);
}
__device__ __forceinline__ void upd2(float ma, int ea, float mb, int eb,
                                     float p, float& mo, int& eo) {
    int em = max(ea, eb);
    float sa = __int_as_float(max(ea - em + 127, 0) << 23);
    float sb = __int_as_float(max(eb - em + 127, 0) << 23);
    float s  = fmaf(mb, sb, ma * sa);
    float mp = p * s;
    int bb = __float_as_int(mp);
    eo = em + ((bb >> 23) - 127);
    mo = __int_as_float((bb & 0x007FFFFF) | 0x3F800000);
}
__device__ __forceinline__ float pow2c(int dp127) {   // 2^d, d<=0, clamped
    return __int_as_float(max(dp127, 0) << 23);
}

__global__ void __launch_bounds__(NT, 1)
ctc_forward_kernel(const float* __restrict__ elog, const float* __restrict__ plog,
                   const int* __restrict__ etgt, const int* __restrict__ ptgt,
                   const int* __restrict__ eil,  const int* __restrict__ pil,
                   const int* __restrict__ etl,  const int* __restrict__ ptl,
                   float* __restrict__ out)
{
    __shared__ float sD[TMAX];        // log2 softmax denominator per timestep
    __shared__ float sStage[2][64];   // staged log2-prob row: x*log2e - D[t]
    __shared__ uint2 sBnd[2][4];      // warp-boundary slot3 (m,e), double-buffered
    __shared__ float sFm[NT * 4];     // final mantissas
    __shared__ int   sFe[NT * 4];     // final exponents
    __shared__ int   sLast;

    const int task = blockIdx.x >> 5;   // 0 = error (C=4), 1 = phoneme (C=64)
    const int b    = blockIdx.x & 31;
    const int tid  = threadIdx.x;
    const int lane = tid & 31;
    const int wid  = tid >> 5;

    const float* logits;
    const int*   targets;
    int C, S, ilen, tlen;
    if (task == 0) {
        C = 4;  S = 50;
        logits  = elog + (size_t)b * TMAX * 4;
        targets = etgt + b * 50;
        ilen = eil[b]; tlen = etl[b];
    } else {
        C = 64; S = 200;
        logits  = plog + (size_t)b * TMAX * 64;
        targets = ptgt + b * 200;
        ilen = pil[b]; tlen = ptl[b];
    }
    const int L    = 2 * S + 1;
    const int Teff = min(TMAX, max(ilen, 1));

    // ---------- Phase 1: log2-sum-exp denominators ----------
    for (int t = tid; t < Teff; t += NT) {
        const float* row = logits + (size_t)t * C;
        float s = 0.f;
        for (int k = 0; k < C; k += 4) {
            float4 v = *reinterpret_cast<const float4*>(row + k);
            s += ex2(v.x * LOG2E) + ex2(v.y * LOG2E)
               + ex2(v.z * LOG2E) + ex2(v.w * LOG2E);
        }
        sD[t] = lg2(s);
    }
    __syncthreads();

    // ---------- Per-thread slot setup: l = 4*tid + {0,1,2,3} ----------
    const int  l0 = 4 * tid;
    const bool v0 = (l0     < L), v1 = (l0 + 1 < L),
               v2 = (l0 + 2 < L), v3 = (l0 + 3 < L);
    const int  j1  = min(2 * tid,     S - 1);
    const int  j1m = max(2 * tid - 1, 0);
    const int  j3  = min(2 * tid + 1, S - 1);
    const int  ext1 = targets[j1];
    const int  ext3 = targets[j3];
    const bool skip1 = (tid >= 1) && (ext1 != targets[j1m]);
    const bool skip3 = (ext3 != ext1);

    // ---------- alpha init (t = 0) ----------
    float m0 = 1.f, m1 = 1.f, m2 = 1.f, m3 = 1.f;
    int   e0 = EDEAD, e1 = EDEAD, e2 = EDEAD, e3 = EDEAD;
    if (tid == 0) {
        float a = ex2(fmaxf(fmaf(logits[0],    LOG2E, -sD[0]), -120.f));
        int bb = __float_as_int(a);
        e0 = (bb >> 23) - 127; m0 = __int_as_float((bb & 0x007FFFFF) | 0x3F800000);
        a = ex2(fmaxf(fmaf(logits[ext1], LOG2E, -sD[0]), -120.f));
        bb = __float_as_int(a);
        e1 = (bb >> 23) - 127; m1 = __int_as_float((bb & 0x007FFFFF) | 0x3F800000);
    }
    if (lane == 31) sBnd[0][wid] = make_uint2(__float_as_uint(m3), (unsigned)e3);

    if (tid < C && 1 < Teff) sStage[1][tid] = fmaf(logits[C + tid], LOG2E, -sD[1]);
    float gpre = 0.f;
    if (tid < C && 2 < Teff) gpre = logits[(size_t)2 * C + tid];
    __syncthreads();

    // Prefetch symbol probs for step t=1 (linear domain, normal floats).
    float pb = ex2(fmaxf(sStage[1][0],    -120.f));
    float p1 = ex2(fmaxf(sStage[1][ext1], -120.f));
    float p3 = ex2(fmaxf(sStage[1][ext3], -120.f));

    // ---------- Phase 2: forward scan ----------
    for (int t = 1; t < Teff; ++t) {
        const int pp = t & 1, q = pp ^ 1;

        // Stage row t+1 (prefetched last iteration); prefetch row t+2.
        if (tid < C) {
            if (t + 1 < Teff) sStage[q][tid] = fmaf(gpre, LOG2E, -sD[t + 1]);
            if (t + 2 < Teff) gpre = logits[(size_t)(t + 2) * C + tid];
        }

        // Left neighbor's OLD slot 3 (only cross-thread operand).
        float nm3 = __shfl_up_sync(0xffffffffu, m3, 1);
        int   ne3 = __shfl_up_sync(0xffffffffu, e3, 1);
        if (lane == 0) {
            if (wid > 0) {
                uint2 v = sBnd[q][wid - 1];
                nm3 = __uint_as_float(v.x); ne3 = (int)v.y;
            } else { nm3 = 1.f; ne3 = EDEAD; }
        }

        float o0m, o1m, o2m, o3m; int o0e, o1e, o2e, o3e;
        upd2(m0, e0, nm3, ne3, pb, o0m, o0e);                           // blank
        upd3(m1, e1, m0, e0, nm3, skip1 ? ne3 : EDEAD, p1, o1m, o1e);   // sym1
        upd2(m2, e2, m1, e1, pb, o2m, o2e);                             // blank
        upd3(m3, e3, m2, e2, m1, skip3 ? e1 : EDEAD, p3, o3m, o3e);     // sym3

        m0 = o0m; e0 = v0 ? o0e : EDEAD;
        m1 = o1m; e1 = v1 ? o1e : EDEAD;
        m2 = o2m; e2 = v2 ? o2e : EDEAD;
        m3 = o3m; e3 = v3 ? o3e : EDEAD;

        if (lane == 31) sBnd[pp][wid] = make_uint2(__float_as_uint(m3), (unsigned)e3);

        __syncthreads();

        // Prefetch symbol probs for step t+1 (off the critical path).
        pb = ex2(fmaxf(sStage[q][0],    -120.f));
        p1 = ex2(fmaxf(sStage[q][ext1], -120.f));
        p3 = ex2(fmaxf(sStage[q][ext3], -120.f));
    }

    // ---------- Publish final alphas ----------
    sFm[l0] = m0; sFe[l0] = e0;
    sFm[l0 + 1] = m1; sFe[l0 + 1] = e1;
    sFm[l0 + 2] = m2; sFe[l0 + 2] = e2;
    sFm[l0 + 3] = m3; sFe[l0 + 3] = e3;
    __syncthreads();

    // ---------- Final loss + fused deterministic reduction ----------
    if (tid == 0) {
        const int iL = 2 * tlen - 1, iB = 2 * tlen;
        int   eL = sFe[iL], eB = sFe[iB];
        float mL = sFm[iL], mB = sFm[iB];
        int   em = max(eL, eB);
        float ss = mL * pow2c(eL + 127 - em) + mB * pow2c(eB + 127 - em);
        float loss = -((float)em + lg2(ss)) * LN2;     // nats
        if (em < -(1 << 27)) loss = 0.f;               // no feasible path => inf
        if (!(loss <= 1e29f)) loss = 0.f;              // zero_infinity / NaN
        g_partial[blockIdx.x] = loss / (float)tlen * (1.0f / BATCH);
        __threadfence();
        unsigned tk = atomicAdd(&g_count, 1u);
        sLast = (tk == 63u);
    }
    __syncthreads();
    if (sLast && tid == 0) {
        __threadfence();
        float s = 0.f;
        #pragma unroll
        for (int i = 0; i < 64; ++i) {
            float v;
            asm volatile("ld.global.cg.f32 %0, [%1];" : "=f"(v) : "l"(g_partial + i));
            s += v;
        }
        out[0] = s;
        g_count = 0;   // reset for graph replay
    }
}

extern "C" void kernel_launch(void* const* d_in, const int* in_sizes, int n_in,
                              void* d_out, int out_size)
{
    const float* elog = (const float*)d_in[0];
    const float* plog = (const float*)d_in[1];
    const int*   etgt = (const int*)d_in[2];
    const int*   ptgt = (const int*)d_in[3];
    const int*   eil  = (const int*)d_in[4];
    const int*   pil  = (const int*)d_in[5];
    const int*   etl  = (const int*)d_in[6];
    const int*   ptl  = (const int*)d_in[7];
    float* out = (float*)d_out;

    ctc_forward_kernel<<<64, NT>>>(elog, plog, etgt, ptgt,
                                   eil, pil, etl, ptl, out);
}